// round 4
// baseline (speedup 1.0000x reference)
#include <cuda_runtime.h>
#include <cuda_bf16.h>
#include <cstdint>

// Fused SIREN MLP: 3 -> 256 -> 256 -> 256 -> 256 -> 3
// Round 3: 512 threads (4 warps/SMSP), f32x2 packed FMA mainloop,
// hidden-layer sin via odd minimax polynomial (valid: |z| <= 1.31 < pi/2,
// relative error <= ~5e-7 worst case), evaluated in packed f32x2.

#define HID 256
#define PTILE 64
#define HS 68              // smem activation row stride (floats), 16B aligned
#define NTHREADS 512
#define NPT 4              // neurons per thread
#define PPT 8              // points per thread

typedef unsigned long long ull;

__device__ __forceinline__ ull fma2(ull a, ull b, ull c) {
    ull d;
    asm("fma.rn.f32x2 %0, %1, %2, %3;" : "=l"(d) : "l"(a), "l"(b), "l"(c));
    return d;
}

__device__ __forceinline__ ull mul2(ull a, ull b) {
    ull d;
    asm("mul.rn.f32x2 %0, %1, %2;" : "=l"(d) : "l"(a), "l"(b));
    return d;
}

__device__ __forceinline__ ull add2(ull a, ull b) {
    ull d;
    asm("add.rn.f32x2 %0, %1, %2;" : "=l"(d) : "l"(a), "l"(b));
    return d;
}

__device__ __forceinline__ ull pack2(float v) {
    ull d;
    asm("mov.b64 %0, {%1, %1};" : "=l"(d) : "f"(v));
    return d;
}

// Packed sin for |x| <= pi/2: x + x^3*(c3 + x2*(c5 + x2*(c7 + x2*c9)))
// Relative error ~1e-8 over the needed range (|z| <= 1.31).
__device__ __forceinline__ ull sin2_small(ull x, ull c3, ull c5, ull c7, ull c9) {
    ull x2 = mul2(x, x);
    ull x3 = mul2(x2, x);
    ull p = fma2(c9, x2, c7);
    p = fma2(p, x2, c5);
    p = fma2(p, x2, c3);
    return fma2(p, x3, x);
}

// One hidden GEMM layer + bias + poly-sin.  hin/hout: [256][HS] in smem.
// Thread handles neurons {m, m+64, m+128, m+192}, points [pbase, pbase+8).
__device__ __forceinline__ void hidden_layer(
    const float* __restrict__ W, const float* __restrict__ b,
    const float* __restrict__ hin, float* __restrict__ hout,
    int m, int pbase)
{
    ull acc[NPT][PPT / 2];
#pragma unroll
    for (int n = 0; n < NPT; n++)
#pragma unroll
        for (int j = 0; j < PPT / 2; j++) acc[n][j] = 0ull;

    const float* w0 = W + (m +   0) * HID;
    const float* w1 = W + (m +  64) * HID;
    const float* w2 = W + (m + 128) * HID;
    const float* w3 = W + (m + 192) * HID;
    const float* hp = hin + pbase;

#pragma unroll 2
    for (int i = 0; i < HID; i += 4) {
        float4 a0 = *reinterpret_cast<const float4*>(w0 + i);
        float4 a1 = *reinterpret_cast<const float4*>(w1 + i);
        float4 a2 = *reinterpret_cast<const float4*>(w2 + i);
        float4 a3 = *reinterpret_cast<const float4*>(w3 + i);
        float wv[NPT][4] = {
            {a0.x, a0.y, a0.z, a0.w},
            {a1.x, a1.y, a1.z, a1.w},
            {a2.x, a2.y, a2.z, a2.w},
            {a3.x, a3.y, a3.z, a3.w},
        };
#pragma unroll
        for (int d = 0; d < 4; d++) {
            const ulonglong2* hr =
                reinterpret_cast<const ulonglong2*>(hp + (i + d) * HS);
            ulonglong2 h0 = hr[0];
            ulonglong2 h1 = hr[1];
#pragma unroll
            for (int n = 0; n < NPT; n++) {
                ull w2p = pack2(wv[n][d]);
                acc[n][0] = fma2(w2p, h0.x, acc[n][0]);
                acc[n][1] = fma2(w2p, h0.y, acc[n][1]);
                acc[n][2] = fma2(w2p, h1.x, acc[n][2]);
                acc[n][3] = fma2(w2p, h1.y, acc[n][3]);
            }
        }
    }

    // epilogue: bias + polynomial sin (|z| <= 1.31 < pi/2, proven bound)
    const ull c3 = pack2(-1.6666667e-1f);
    const ull c5 = pack2( 8.3333310e-3f);
    const ull c7 = pack2(-1.9841271e-4f);
    const ull c9 = pack2( 2.7557314e-6f);
#pragma unroll
    for (int n = 0; n < NPT; n++) {
        int o = m + n * 64;
        ull bb2 = pack2(__ldg(b + o));
        float* orow = hout + o * HS + pbase;
#pragma unroll
        for (int j = 0; j < PPT / 2; j++) {
            ull z = add2(acc[n][j], bb2);
            ull s = sin2_small(z, c3, c5, c7, c9);
            *reinterpret_cast<ull*>(orow + 2 * j) = s;
        }
    }
}

__global__ void __launch_bounds__(NTHREADS, 1) siren_fused_kernel(
    const float* __restrict__ x,
    const float* __restrict__ W0, const float* __restrict__ b0,
    const float* __restrict__ W1, const float* __restrict__ b1,
    const float* __restrict__ W2, const float* __restrict__ b2,
    const float* __restrict__ W3, const float* __restrict__ b3,
    const float* __restrict__ W4, const float* __restrict__ b4,
    float* __restrict__ out, int npts)
{
    extern __shared__ float sm[];
    float* hA = sm;                       // [256][HS]
    float* hB = sm + HID * HS;            // [256][HS]
    float* xs = sm + 2 * HID * HS;        // [64*3]

    const int tid = threadIdx.x;
    const int m = tid & 63;               // neuron sub-index
    const int pbase = (tid >> 6) * PPT;   // point group (0..7)*8
    const int tile0 = blockIdx.x * PTILE;

    // stage x tile (64 points x 3) into smem
    if (tid < PTILE * 3) {
        int idx = tile0 * 3 + tid;
        xs[tid] = (idx < npts * 3) ? x[idx] : 0.0f;
    }
    __syncthreads();

    // ---- layer 0: h = sin(30*(W0 x + b0)) -> hA  (accurate sinf, |z|<=~30)
    {
#pragma unroll
        for (int n = 0; n < NPT; n++) {
            int o = m + n * 64;
            float w0 = __ldg(W0 + o * 3 + 0);
            float w1 = __ldg(W0 + o * 3 + 1);
            float w2 = __ldg(W0 + o * 3 + 2);
            float bb = __ldg(b0 + o);
            float* orow = hA + o * HS + pbase;
#pragma unroll
            for (int p = 0; p < PPT; p += 2) {
                const float* xp = xs + (pbase + p) * 3;
                float z0 = 30.0f * (w0 * xp[0] + w1 * xp[1] + w2 * xp[2] + bb);
                float z1 = 30.0f * (w0 * xp[3] + w1 * xp[4] + w2 * xp[5] + bb);
                *reinterpret_cast<float2*>(orow + p) =
                    make_float2(sinf(z0), sinf(z1));
            }
        }
    }
    __syncthreads();

    // ---- hidden layers ----
    hidden_layer(W1, b1, hA, hB, m, pbase);
    __syncthreads();
    hidden_layer(W2, b2, hB, hA, m, pbase);
    __syncthreads();
    hidden_layer(W3, b3, hA, hB, m, pbase);
    __syncthreads();

    // ---- layer 4: out[p][c] = W4[c] . h3[:,p] + b4[c]  (reads hB) ----
    if (tid < PTILE * 3) {
        int c = tid / PTILE;       // 0..2
        int p = tid % PTILE;       // 0..63
        const float* w = W4 + c * HID;
        float acc = 0.0f;
#pragma unroll 8
        for (int i = 0; i < HID; i += 4) {
            float4 wv = *reinterpret_cast<const float4*>(w + i);
            acc += wv.x * hB[(i + 0) * HS + p];
            acc += wv.y * hB[(i + 1) * HS + p];
            acc += wv.z * hB[(i + 2) * HS + p];
            acc += wv.w * hB[(i + 3) * HS + p];
        }
        int prow = tile0 + p;
        if (prow < npts)
            out[prow * 3 + c] = acc + __ldg(b4 + c);
    }
}

extern "C" void kernel_launch(void* const* d_in, const int* in_sizes, int n_in,
                              void* d_out, int out_size) {
    const float* x  = (const float*)d_in[0];
    const float* W0 = (const float*)d_in[1];
    const float* b0 = (const float*)d_in[2];
    const float* W1 = (const float*)d_in[3];
    const float* b1 = (const float*)d_in[4];
    const float* W2 = (const float*)d_in[5];
    const float* b2 = (const float*)d_in[6];
    const float* W3 = (const float*)d_in[7];
    const float* b3 = (const float*)d_in[8];
    const float* W4 = (const float*)d_in[9];
    const float* b4 = (const float*)d_in[10];
    float* out = (float*)d_out;

    int npts = in_sizes[0] / 3;
    int nblocks = (npts + PTILE - 1) / PTILE;

    size_t smem = (2 * HID * HS + PTILE * 3) * sizeof(float);  // 140,032 B
    cudaFuncSetAttribute(siren_fused_kernel,
                         cudaFuncAttributeMaxDynamicSharedMemorySize,
                         (int)smem);

    siren_fused_kernel<<<nblocks, NTHREADS, smem>>>(
        x, W0, b0, W1, b1, W2, b2, W3, b3, W4, b4, out, npts);
}

// round 5
// speedup vs baseline: 1.7828x; 1.7828x over previous
#include <cuda_runtime.h>
#include <cuda_bf16.h>
#include <cstdint>

// Fused SIREN MLP: 3 -> 256 -> 256 -> 256 -> 256 -> 3
// Round 4: warp = 16 neurons x 64 points (lane = point pair {l, l+32}).
//  - weight LDG.128 uniform across warp (1 cache line / instruction)
//  - K-packed f32x2: fma2((W[k],W[k+1]), (h[k],h[k+1]), acc), fold lo+hi at end
//    -> zero packing MOVs, weight pairs come straight out of LDG.128
//  - activations transposed in smem: h[point][k], row stride 260 floats
//    (16B aligned, conflict-free LDS.128 phases)

#define HID 256
#define PTILE 64
#define HROW 260           // floats per point-row (1040B: 16B aligned, bank-safe)
#define NTHREADS 512

typedef unsigned long long ull;

__device__ __forceinline__ ull fma2(ull a, ull b, ull c) {
    ull d;
    asm("fma.rn.f32x2 %0, %1, %2, %3;" : "=l"(d) : "l"(a), "l"(b), "l"(c));
    return d;
}

// sin for |x| <= pi/2 (+eps), relative error ~1e-8 at small x by construction
__device__ __forceinline__ float sin_small(float x) {
    float x2 = x * x;
    float p = fmaf(2.7557314e-6f, x2, -1.9841271e-4f);
    p = fmaf(p, x2, 8.3333310e-3f);
    p = fmaf(p, x2, -1.6666667e-1f);
    return fmaf(p * x2, x, x);
}

// accurate sin for |z| <= ~32 via Cody-Waite reduction by pi
__device__ __forceinline__ float sin_cw(float z) {
    float k = rintf(z * 0.318309886183790672f);
    float r = fmaf(k, -3.14159274101257324f, z);   // z - k*PI_HI
    r = fmaf(k, 8.74227800296169792e-8f, r);       // + k*(PI_HI - pi)
    float s = sin_small(r);
    int ki = (int)k;
    return (ki & 1) ? -s : s;
}

// One hidden GEMM layer + bias + sin.  hin/hout: [64 pts][HROW] in smem.
// Warp w owns neurons [16w, 16w+16); lane l owns points l and l+32.
__device__ __forceinline__ void hidden_layer(
    const float* __restrict__ W, const float* __restrict__ b,
    const float* __restrict__ hin, float* __restrict__ hout,
    int ob, int p0, int p1)
{
    const float* h0row = hin + p0 * HROW;
    const float* h1row = hin + p1 * HROW;

#pragma unroll
    for (int half = 0; half < 2; half++) {
        const int obh = ob + half * 8;
        const float* wbase = W + obh * HID;

        ull acc[8][2];
#pragma unroll
        for (int j = 0; j < 8; j++) { acc[j][0] = 0ull; acc[j][1] = 0ull; }

#pragma unroll 8
        for (int kb = 0; kb < HID; kb += 4) {
            // activation quads for this lane's two points (k-pairs)
            ulonglong2 h0 = *reinterpret_cast<const ulonglong2*>(h0row + kb);
            ulonglong2 h1 = *reinterpret_cast<const ulonglong2*>(h1row + kb);
#pragma unroll
            for (int j = 0; j < 8; j++) {
                // (W[o][kb],W[o][kb+1]) , (W[o][kb+2],W[o][kb+3]) pre-paired
                ulonglong2 wq = *reinterpret_cast<const ulonglong2*>(
                    wbase + j * HID + kb);
                acc[j][0] = fma2(wq.x, h0.x, acc[j][0]);
                acc[j][1] = fma2(wq.x, h1.x, acc[j][1]);
                acc[j][0] = fma2(wq.y, h0.y, acc[j][0]);
                acc[j][1] = fma2(wq.y, h1.y, acc[j][1]);
            }
        }

        // epilogue: fold even/odd-k partials, bias, sin, store transposed
#pragma unroll
        for (int j = 0; j < 8; j++) {
            int o = obh + j;
            float bb = __ldg(b + o);
            float2 a0 = *reinterpret_cast<float2*>(&acc[j][0]);
            float2 a1 = *reinterpret_cast<float2*>(&acc[j][1]);
            hout[p0 * HROW + o] = sin_small(a0.x + a0.y + bb);
            hout[p1 * HROW + o] = sin_small(a1.x + a1.y + bb);
        }
    }
}

__global__ void __launch_bounds__(NTHREADS, 1) siren_fused_kernel(
    const float* __restrict__ x,
    const float* __restrict__ W0, const float* __restrict__ b0,
    const float* __restrict__ W1, const float* __restrict__ b1,
    const float* __restrict__ W2, const float* __restrict__ b2,
    const float* __restrict__ W3, const float* __restrict__ b3,
    const float* __restrict__ W4, const float* __restrict__ b4,
    float* __restrict__ out, int npts)
{
    extern __shared__ float sm[];
    float* hA = sm;                        // [64][HROW]
    float* hB = sm + PTILE * HROW;         // [64][HROW]
    float* xs = sm + 2 * PTILE * HROW;     // [64*3]

    const int tid = threadIdx.x;
    const int w = tid >> 5;
    const int l = tid & 31;
    const int p0 = l;
    const int p1 = l + 32;
    const int ob = w * 16;                 // 16 neurons per warp
    const int tile0 = blockIdx.x * PTILE;

    // stage x tile (64 points x 3)
    if (tid < PTILE * 3) {
        int idx = tile0 * 3 + tid;
        xs[tid] = (idx < npts * 3) ? x[idx] : 0.0f;
    }
    __syncthreads();

    // ---- layer 0: h0[p][o] = sin(30*(W0 x + b0)), accurate sin ----
    {
        float xa0 = xs[p0 * 3 + 0], xa1 = xs[p0 * 3 + 1], xa2 = xs[p0 * 3 + 2];
        float xb0 = xs[p1 * 3 + 0], xb1 = xs[p1 * 3 + 1], xb2 = xs[p1 * 3 + 2];
#pragma unroll
        for (int n = 0; n < 16; n++) {
            int o = ob + n;
            float w0 = __ldg(W0 + 3 * o + 0);
            float w1 = __ldg(W0 + 3 * o + 1);
            float w2 = __ldg(W0 + 3 * o + 2);
            float bb = __ldg(b0 + o);
            float za = 30.0f * (fmaf(w0, xa0, fmaf(w1, xa1, fmaf(w2, xa2, bb))));
            float zb = 30.0f * (fmaf(w0, xb0, fmaf(w1, xb1, fmaf(w2, xb2, bb))));
            hA[p0 * HROW + o] = sin_cw(za);
            hA[p1 * HROW + o] = sin_cw(zb);
        }
    }
    __syncthreads();

    // ---- hidden layers ----
    hidden_layer(W1, b1, hA, hB, ob, p0, p1);
    __syncthreads();
    hidden_layer(W2, b2, hB, hA, ob, p0, p1);
    __syncthreads();
    hidden_layer(W3, b3, hA, hB, ob, p0, p1);
    __syncthreads();

    // ---- layer 4: out[p][c] = W4[c] . h3[p][:] + b4[c]  (reads hB) ----
    if (tid < PTILE * 3) {
        int c = tid >> 6;            // 0..2 (uniform per warp)
        int p = tid & 63;
        const float* hrow = hB + p * HROW;
        const float* wrow = W4 + c * HID;
        ull acc0 = 0ull, acc1 = 0ull;
#pragma unroll 8
        for (int kb = 0; kb < HID; kb += 4) {
            ulonglong2 hq = *reinterpret_cast<const ulonglong2*>(hrow + kb);
            ulonglong2 wq = *reinterpret_cast<const ulonglong2*>(wrow + kb);
            acc0 = fma2(wq.x, hq.x, acc0);
            acc1 = fma2(wq.y, hq.y, acc1);
        }
        float2 a0 = *reinterpret_cast<float2*>(&acc0);
        float2 a1 = *reinterpret_cast<float2*>(&acc1);
        float v = a0.x + a0.y + a1.x + a1.y + __ldg(b4 + c);
        int prow = tile0 + p;
        if (prow < npts) out[prow * 3 + c] = v;
    }
}

extern "C" void kernel_launch(void* const* d_in, const int* in_sizes, int n_in,
                              void* d_out, int out_size) {
    const float* x  = (const float*)d_in[0];
    const float* W0 = (const float*)d_in[1];
    const float* b0 = (const float*)d_in[2];
    const float* W1 = (const float*)d_in[3];
    const float* b1 = (const float*)d_in[4];
    const float* W2 = (const float*)d_in[5];
    const float* b2 = (const float*)d_in[6];
    const float* W3 = (const float*)d_in[7];
    const float* b3 = (const float*)d_in[8];
    const float* W4 = (const float*)d_in[9];
    const float* b4 = (const float*)d_in[10];
    float* out = (float*)d_out;

    int npts = in_sizes[0] / 3;
    int nblocks = (npts + PTILE - 1) / PTILE;

    size_t smem = (2 * PTILE * HROW + PTILE * 3) * sizeof(float);  // 133,888 B
    cudaFuncSetAttribute(siren_fused_kernel,
                         cudaFuncAttributeMaxDynamicSharedMemorySize,
                         (int)smem);

    siren_fused_kernel<<<nblocks, NTHREADS, smem>>>(
        x, W0, b0, W1, b1, W2, b2, W3, b3, W4, b4, out, npts);
}

// round 6
// speedup vs baseline: 2.3642x; 1.3261x over previous
#include <cuda_runtime.h>
#include <cuda_bf16.h>
#include <cstdint>

// Fused SIREN MLP: 3 -> 256 -> 256 -> 256 -> 256 -> 3
// Round 5: weights staged through double-buffered SMEM chunks; mainloop weight
// reads are warp-uniform LDS.128 (true smem broadcast, ~1 wavefront) instead of
// per-thread LDG.128 (~4 wavefronts even when broadcast).  16 neurons per
// inner iteration so activation quads are loaded once per k-step.
// warp = 16 neurons x 64 points, lane = points {l, l+32}, K-packed f32x2.

#define HID 256
#define PTILE 64
#define HROW 260           // smem act row stride (floats); 8-lane phases conflict-free
#define NTHREADS 512
#define KC 16              // k-chunk size (floats per neuron per chunk)
#define NCHUNK (HID / KC)  // 16
#define WCHUNK (HID * KC)  // floats per chunk buffer (4096)

typedef unsigned long long ull;

__device__ __forceinline__ ull fma2(ull a, ull b, ull c) {
    ull d;
    asm("fma.rn.f32x2 %0, %1, %2, %3;" : "=l"(d) : "l"(a), "l"(b), "l"(c));
    return d;
}

// sin for |x| <= pi/2 (+eps); relatively exact at small x by construction
__device__ __forceinline__ float sin_small(float x) {
    float x2 = x * x;
    float p = fmaf(2.7557314e-6f, x2, -1.9841271e-4f);
    p = fmaf(p, x2, 8.3333310e-3f);
    p = fmaf(p, x2, -1.6666667e-1f);
    return fmaf(p * x2, x, x);
}

// accurate sin for |z| <= ~32 via Cody-Waite reduction by pi
__device__ __forceinline__ float sin_cw(float z) {
    float k = rintf(z * 0.318309886183790672f);
    float r = fmaf(k, -3.14159274101257324f, z);
    r = fmaf(k, 8.74227800296169792e-8f, r);
    float s = sin_small(r);
    int ki = (int)k;
    return (ki & 1) ? -s : s;
}

// One hidden layer: GEMM (smem-staged weights) + bias + poly sin.
// hin/hout: [64 pts][HROW].  wbuf: [2][WCHUNK] scratch.
__device__ __forceinline__ void hidden_layer(
    const float* __restrict__ W, const float* __restrict__ b,
    const float* __restrict__ hin, float* __restrict__ hout,
    float* __restrict__ wbuf,
    int ob, int p0, int p1, int tid)
{
    // staging indices: chunk = 256 rows x KC floats = 1024 float4 slots,
    // 2 slots per thread.  slot s -> row o = s>>2, quad q = s&3.
    const int s0 = tid, s1 = tid + NTHREADS;
    const int o0 = s0 >> 2, q0 = (s0 & 3) * 4;
    const int o1 = s1 >> 2, q1 = (s1 & 3) * 4;

    // stage chunk 0 into buffer 0
    {
        float4 v0 = *reinterpret_cast<const float4*>(W + o0 * HID + q0);
        float4 v1 = *reinterpret_cast<const float4*>(W + o1 * HID + q1);
        *reinterpret_cast<float4*>(wbuf + o0 * KC + q0) = v0;
        *reinterpret_cast<float4*>(wbuf + o1 * KC + q1) = v1;
    }

    ull acc[16][2];
#pragma unroll
    for (int j = 0; j < 16; j++) { acc[j][0] = 0ull; acc[j][1] = 0ull; }

    __syncthreads();

#pragma unroll 1
    for (int c = 0; c < NCHUNK; c++) {
        // prefetch next chunk from GMEM early (lands during compute)
        float4 v0, v1;
        if (c + 1 < NCHUNK) {
            const float* Wn = W + (c + 1) * KC;
            v0 = *reinterpret_cast<const float4*>(Wn + o0 * HID + q0);
            v1 = *reinterpret_cast<const float4*>(Wn + o1 * HID + q1);
        }

        const float* wb = wbuf + (c & 1) * WCHUNK + ob * KC;
        const float* h0p = hin + p0 * HROW + c * KC;
        const float* h1p = hin + p1 * HROW + c * KC;

#pragma unroll
        for (int kb = 0; kb < KC; kb += 4) {
            ulonglong2 h0 = *reinterpret_cast<const ulonglong2*>(h0p + kb);
            ulonglong2 h1 = *reinterpret_cast<const ulonglong2*>(h1p + kb);
#pragma unroll
            for (int j = 0; j < 16; j++) {
                // warp-uniform address -> smem broadcast
                ulonglong2 wq = *reinterpret_cast<const ulonglong2*>(
                    wb + j * KC + kb);
                acc[j][0] = fma2(wq.x, h0.x, acc[j][0]);
                acc[j][1] = fma2(wq.x, h1.x, acc[j][1]);
                acc[j][0] = fma2(wq.y, h0.y, acc[j][0]);
                acc[j][1] = fma2(wq.y, h1.y, acc[j][1]);
            }
        }

        if (c + 1 < NCHUNK) {
            float* wn = wbuf + ((c + 1) & 1) * WCHUNK;
            *reinterpret_cast<float4*>(wn + o0 * KC + q0) = v0;
            *reinterpret_cast<float4*>(wn + o1 * KC + q1) = v1;
        }
        __syncthreads();
    }

    // epilogue: fold even/odd-k partials, bias, poly sin, store transposed
#pragma unroll
    for (int j = 0; j < 16; j++) {
        int o = ob + j;
        float bb = __ldg(b + o);
        float2 a0 = *reinterpret_cast<float2*>(&acc[j][0]);
        float2 a1 = *reinterpret_cast<float2*>(&acc[j][1]);
        hout[p0 * HROW + o] = sin_small(a0.x + a0.y + bb);
        hout[p1 * HROW + o] = sin_small(a1.x + a1.y + bb);
    }
}

__global__ void __launch_bounds__(NTHREADS, 1) siren_fused_kernel(
    const float* __restrict__ x,
    const float* __restrict__ W0, const float* __restrict__ b0,
    const float* __restrict__ W1, const float* __restrict__ b1,
    const float* __restrict__ W2, const float* __restrict__ b2,
    const float* __restrict__ W3, const float* __restrict__ b3,
    const float* __restrict__ W4, const float* __restrict__ b4,
    float* __restrict__ out, int npts)
{
    extern __shared__ float sm[];
    float* hA   = sm;                          // [64][HROW]
    float* hB   = sm + PTILE * HROW;           // [64][HROW]
    float* wbuf = sm + 2 * PTILE * HROW;       // [2][WCHUNK]
    float* xs   = wbuf + 2 * WCHUNK;           // [64*3]

    const int tid = threadIdx.x;
    const int w = tid >> 5;
    const int l = tid & 31;
    const int p0 = l;
    const int p1 = l + 32;
    const int ob = w * 16;                     // 16 neurons per warp
    const int tile0 = blockIdx.x * PTILE;

    // stage x tile (64 points x 3)
    if (tid < PTILE * 3) {
        int idx = tile0 * 3 + tid;
        xs[tid] = (idx < npts * 3) ? x[idx] : 0.0f;
    }
    __syncthreads();

    // ---- layer 0: h0[p][o] = sin(30*(W0 x + b0)), accurate sin ----
    {
        float xa0 = xs[p0 * 3 + 0], xa1 = xs[p0 * 3 + 1], xa2 = xs[p0 * 3 + 2];
        float xb0 = xs[p1 * 3 + 0], xb1 = xs[p1 * 3 + 1], xb2 = xs[p1 * 3 + 2];
#pragma unroll
        for (int n = 0; n < 16; n++) {
            int o = ob + n;
            float w0 = __ldg(W0 + 3 * o + 0);
            float w1 = __ldg(W0 + 3 * o + 1);
            float w2 = __ldg(W0 + 3 * o + 2);
            float bb = __ldg(b0 + o);
            float za = 30.0f * fmaf(w0, xa0, fmaf(w1, xa1, fmaf(w2, xa2, bb)));
            float zb = 30.0f * fmaf(w0, xb0, fmaf(w1, xb1, fmaf(w2, xb2, bb)));
            hA[p0 * HROW + o] = sin_cw(za);
            hA[p1 * HROW + o] = sin_cw(zb);
        }
    }
    __syncthreads();

    // ---- hidden layers ----
    hidden_layer(W1, b1, hA, hB, wbuf, ob, p0, p1, tid);
    __syncthreads();
    hidden_layer(W2, b2, hB, hA, wbuf, ob, p0, p1, tid);
    __syncthreads();
    hidden_layer(W3, b3, hA, hB, wbuf, ob, p0, p1, tid);
    __syncthreads();

    // ---- layer 4: out[p][c] = W4[c] . h3[p][:] + b4[c]  (reads hB) ----
    if (tid < PTILE * 3) {
        int c = tid >> 6;            // 0..2 (uniform per warp)
        int p = tid & 63;
        const float* hrow = hB + p * HROW;
        const float* wrow = W4 + c * HID;
        ull acc0 = 0ull, acc1 = 0ull;
#pragma unroll 8
        for (int kb = 0; kb < HID; kb += 4) {
            ulonglong2 hq = *reinterpret_cast<const ulonglong2*>(hrow + kb);
            ulonglong2 wq = *reinterpret_cast<const ulonglong2*>(wrow + kb);
            acc0 = fma2(wq.x, hq.x, acc0);
            acc1 = fma2(wq.y, hq.y, acc1);
        }
        float2 a0 = *reinterpret_cast<float2*>(&acc0);
        float2 a1 = *reinterpret_cast<float2*>(&acc1);
        float v = a0.x + a0.y + a1.x + a1.y + __ldg(b4 + c);
        int prow = tile0 + p;
        if (prow < npts) out[prow * 3 + c] = v;
    }
}

extern "C" void kernel_launch(void* const* d_in, const int* in_sizes, int n_in,
                              void* d_out, int out_size) {
    const float* x  = (const float*)d_in[0];
    const float* W0 = (const float*)d_in[1];
    const float* b0 = (const float*)d_in[2];
    const float* W1 = (const float*)d_in[3];
    const float* b1 = (const float*)d_in[4];
    const float* W2 = (const float*)d_in[5];
    const float* b2 = (const float*)d_in[6];
    const float* W3 = (const float*)d_in[7];
    const float* b3 = (const float*)d_in[8];
    const float* W4 = (const float*)d_in[9];
    const float* b4 = (const float*)d_in[10];
    float* out = (float*)d_out;

    int npts = in_sizes[0] / 3;
    int nblocks = (npts + PTILE - 1) / PTILE;

    // 2*64*260 + 2*4096 + 192 floats = 166,400 B
    size_t smem = (2 * PTILE * HROW + 2 * WCHUNK + PTILE * 3) * sizeof(float);
    cudaFuncSetAttribute(siren_fused_kernel,
                         cudaFuncAttributeMaxDynamicSharedMemorySize,
                         (int)smem);

    siren_fused_kernel<<<nblocks, NTHREADS, smem>>>(
        x, W0, b0, W1, b1, W2, b2, W3, b3, W4, b4, out, npts);
}